// round 16
// baseline (speedup 1.0000x reference)
#include <cuda_runtime.h>
#include <math.h>
#include <stdint.h>

// VolatilityLoss: mean((std3(pred) - std3(targ))^2), window w=3.
// B=512, S=8192, L=8190 outputs/row.
// HYBRID dual-path kernel: 512 CTAs (one per row) x 256 threads.
//  - Front half (elems 0..4111) via TMA double-buffer (2 chunks of 2048+16).
//  - Back half (elems 4096..8191) via direct LDG packed chain (16/thread),
//    computed WHILE the TMA copies are in flight (separate HW queues).
// Packed-f32x2 rolling chain; 6*var_i = e_i^2+e_{i+1}^2+(e_i+e_{i+1})^2;
// pair via one sqrt; deferred /6.

#define B_ROWS 512
#define S_LEN  8192
#define L_OUT  (S_LEN - 2)
#define NBLOCKS 512           // one per row
#define NTHREADS 256
#define CHUNK 2048            // TMA chunk elems per array
#define EXTRA 16
#define HALF 4096             // front-half elems (TMA), back half is LDG

typedef unsigned long long u64;

__device__ float        g_partials[NBLOCKS];
__device__ unsigned int g_counter = 0;   // monotone across graph replays

__device__ __forceinline__ float sqrt_approx(float x) {
    float r;
    asm("sqrt.approx.f32 %0, %1;" : "=f"(r) : "f"(x));
    return r;
}

__device__ __forceinline__ uint32_t smem_u32(const void* p) {
    uint32_t a;
    asm("{ .reg .u64 t; cvta.to.shared.u64 t, %1; cvt.u32.u64 %0, t; }"
        : "=r"(a) : "l"(p));
    return a;
}

__device__ __forceinline__ void mbar_wait(uint32_t mbar, uint32_t parity) {
    asm volatile(
        "{\n\t.reg .pred P;\n"
        "W%=:\n\t"
        "mbarrier.try_wait.parity.acquire.cta.shared::cta.b64 P, [%0], %1, 0x989680;\n\t"
        "@!P bra W%=;\n\t}"
        :: "r"(mbar), "r"(parity) : "memory");
}

#define PACK2(dst, lo, hi) \
    asm("mov.b64 %0, {%1, %2};" : "=l"(dst) : "f"(lo), "f"(hi))
#define UNPACK2(lo, hi, src) \
    asm("mov.b64 {%0, %1}, %2;" : "=f"(lo), "=f"(hi) : "l"(src))
#define FMA2(dst, a, b, c) \
    asm("fma.rn.f32x2 %0, %1, %2, %3;" : "=l"(dst) : "l"(a), "l"(b), "l"(c))
#define ADD2(dst, a, b) \
    asm("add.rn.f32x2 %0, %1, %2;" : "=l"(dst) : "l"(a), "l"(b))
#define MUL2(dst, a, b) \
    asm("mul.rn.f32x2 %0, %1, %2;" : "=l"(dst) : "l"(a), "l"(b))

// Consume one element pair; completes the window ending 2 elems back (if v).
#define STEP(pel, tel, v)                                   \
    do {                                                    \
        u64 Pn, E, Gc, F, GS, V;                            \
        PACK2(Pn, pel, tel);                                \
        FMA2(E, Pn, M1, Pc);      /* E = Pc - Pn */         \
        MUL2(Gc, E, E);                                     \
        ADD2(F, Ep, E);                                     \
        ADD2(GS, Gp, Gc);                                   \
        FMA2(V, F, F, GS);        /* {6vp, 6vt} >= 0 */     \
        if (v) {                                            \
            ADD2(accV, accV, V);                            \
            float _vp, _vt;                                 \
            UNPACK2(_vp, _vt, V);                           \
            accR += sqrt_approx(_vp * _vt);                 \
        }                                                   \
        Ep = E; Gp = Gc; Pc = Pn;                           \
    } while (0)

__global__ void __launch_bounds__(NTHREADS)
vol_loss_hybrid(const float* __restrict__ pred, const float* __restrict__ targ,
                float* __restrict__ out) {
    __shared__ alignas(16) float sp[2][CHUNK + EXTRA];
    __shared__ alignas(16) float sq[2][CHUNK + EXTRA];
    __shared__ alignas(8)  u64   mbar_store[2];
    __shared__ float red[NTHREADS / 32];
    __shared__ bool  is_last;

    const int t    = threadIdx.x;
    const int lane = t & 31;
    const float* pg = pred + ((size_t)blockIdx.x << 13);
    const float* tg = targ + ((size_t)blockIdx.x << 13);
    const uint32_t mb0 = smem_u32(&mbar_store[0]);
    const uint32_t mb1 = smem_u32(&mbar_store[1]);

    if (t == 0) {
        asm volatile("mbarrier.init.shared::cta.b64 [%0], 1;" :: "r"(mb0) : "memory");
        asm volatile("mbarrier.init.shared::cta.b64 [%0], 1;" :: "r"(mb1) : "memory");
    }
    __syncthreads();

    // ---- Fire both TMA chunks for the FRONT half immediately ----
    if (t == 0) {
        #pragma unroll
        for (int c = 0; c < 2; ++c) {
            const uint32_t mb = c ? mb1 : mb0;
            const uint32_t bytes = (CHUNK + EXTRA) * 4u;
            asm volatile("mbarrier.arrive.expect_tx.shared::cta.b64 _, [%0], %1;"
                         :: "r"(mb), "r"(bytes * 2u) : "memory");
            asm volatile(
                "cp.async.bulk.shared::cluster.global.mbarrier::complete_tx::bytes "
                "[%0], [%1], %2, [%3];"
                :: "r"(smem_u32(sp[c])), "l"(pg + c * CHUNK), "r"(bytes), "r"(mb)
                : "memory");
            asm volatile(
                "cp.async.bulk.shared::cluster.global.mbarrier::complete_tx::bytes "
                "[%0], [%1], %2, [%3];"
                :: "r"(smem_u32(sq[c])), "l"(tg + c * CHUNK), "r"(bytes), "r"(mb)
                : "memory");
        }
    }

    u64 M1, accV;
    PACK2(M1,   -1.0f, -1.0f);
    PACK2(accV,  0.0f,  0.0f);
    float accR = 0.0f;

    // ---- BACK half via direct LDG while TMA streams the front half ----
    {
        const float* pb = pg + HALF + (t << 4);
        const float* tb = tg + HALF + (t << 4);
        float4 pA = ((const float4*)pb)[0];
        float4 pB = ((const float4*)pb)[1];
        float4 pC = ((const float4*)pb)[2];
        float4 pD = ((const float4*)pb)[3];
        float4 tA = ((const float4*)tb)[0];
        float4 tB = ((const float4*)tb)[1];
        float4 tC = ((const float4*)tb)[2];
        float4 tD = ((const float4*)tb)[3];

        // Peek elems 16,17 = lane+1's elems 0,1; lane 31 loads (predicated:
        // thread 255 is the row end, its last two windows are invalid).
        const bool full = (t != NTHREADS - 1);
        float p16 = __shfl_down_sync(0xffffffffu, pA.x, 1);
        float p17 = __shfl_down_sync(0xffffffffu, pA.y, 1);
        float t16 = __shfl_down_sync(0xffffffffu, tA.x, 1);
        float t17 = __shfl_down_sync(0xffffffffu, tA.y, 1);
        if (lane == 31) {
            p16 = p17 = t16 = t17 = 0.0f;
            if (full) {
                float2 pe2 = ((const float2*)(pb + 16))[0];
                float2 te2 = ((const float2*)(tb + 16))[0];
                p16 = pe2.x; p17 = pe2.y; t16 = te2.x; t17 = te2.y;
            }
        }

        u64 P0, Pc, Ep, Gp;
        PACK2(P0, pA.x, tA.x);
        PACK2(Pc, pA.y, tA.y);
        FMA2(Ep, Pc, M1, P0);
        MUL2(Gp, Ep, Ep);
        STEP(pA.z, tA.z, true);  STEP(pA.w, tA.w, true);
        STEP(pB.x, tB.x, true);  STEP(pB.y, tB.y, true);
        STEP(pB.z, tB.z, true);  STEP(pB.w, tB.w, true);
        STEP(pC.x, tC.x, true);  STEP(pC.y, tC.y, true);
        STEP(pC.z, tC.z, true);  STEP(pC.w, tC.w, true);
        STEP(pD.x, tD.x, true);  STEP(pD.y, tD.y, true);
        STEP(pD.z, tD.z, true);  STEP(pD.w, tD.w, true);
        STEP(p16,  t16,  full);  STEP(p17,  t17,  full);
    }

    // ---- FRONT half from SMEM (all windows unconditionally valid) ----
    #pragma unroll
    for (int c = 0; c < 2; ++c) {
        mbar_wait(c ? mb1 : mb0, 0);
        const float* bp = sp[c];
        const float* bq = sq[c];
        #pragma unroll
        for (int p = 0; p < 2; ++p) {
            const int idx = p * (NTHREADS * 4) + (t << 2);
            float4 P  = *(const float4*)&bp[idx];
            float4 T  = *(const float4*)&bq[idx];
            float2 Pp = *(const float2*)&bp[idx + 4];
            float2 Tp = *(const float2*)&bq[idx + 4];

            u64 P0, Pc, Ep, Gp;
            PACK2(P0, P.x, T.x);
            PACK2(Pc, P.y, T.y);
            FMA2(Ep, Pc, M1, P0);
            MUL2(Gp, Ep, Ep);
            STEP(P.z,  T.z,  true);
            STEP(P.w,  T.w,  true);
            STEP(Pp.x, Tp.x, true);
            STEP(Pp.y, Tp.y, true);
        }
    }

    float vps, vts;
    UNPACK2(vps, vts, accV);
    float acc = (vps + vts) - 2.0f * accR;   // still scaled by 6

    // Deterministic intra-block reduction.
    #pragma unroll
    for (int o = 16; o > 0; o >>= 1)
        acc += __shfl_down_sync(0xffffffffu, acc, o);
    if (lane == 0) red[t >> 5] = acc;
    __syncthreads();

    if (t == 0) {
        float v = 0.0f;
        #pragma unroll
        for (int w = 0; w < NTHREADS / 32; ++w) v += red[w];
        g_partials[blockIdx.x] = v;
        __threadfence();
        unsigned int old = atomicAdd(&g_counter, 1u);
        is_last = ((old + 1u) % (unsigned)NBLOCKS) == 0u;
    }
    __syncthreads();

    if (!is_last) return;

    // Last-arriving block: deterministic final reduction; fold deferred /6.
    __shared__ double sh[NTHREADS];
    double s = 0.0;
    for (int i = t; i < NBLOCKS; i += NTHREADS)
        s += (double)g_partials[i];
    sh[t] = s;
    __syncthreads();
    #pragma unroll
    for (int stride = NTHREADS / 2; stride > 0; stride >>= 1) {
        if (t < stride) sh[t] += sh[t + stride];
        __syncthreads();
    }
    if (t == 0)
        out[0] = (float)(sh[0] / (6.0 * (double)B_ROWS * (double)L_OUT));
}

extern "C" void kernel_launch(void* const* d_in, const int* in_sizes, int n_in,
                              void* d_out, int out_size) {
    const float* pred = (const float*)d_in[0];
    const float* targ = (const float*)d_in[1];
    vol_loss_hybrid<<<NBLOCKS, NTHREADS>>>(pred, targ, (float*)d_out);
}